// round 1
// baseline (speedup 1.0000x reference)
#include <cuda_runtime.h>
#include <math.h>

#define DD 512
#define MAXM 100064
#define PV 64

// ---------------- scratch (static device globals; no allocation in kernel_launch) ----
__device__ __align__(16) float g_bufA[(size_t)MAXM * DD];
__device__ __align__(16) float g_bufB[(size_t)MAXM * DD];
__device__ __align__(16) float g_srcb[(size_t)MAXM * 64];
__device__ __align__(16) float g_dstT[64 * 64];
__device__ int g_cmap[MAXM];

__device__ __forceinline__ float elu1(float x) { return x > 0.f ? x : expm1f(x); }

// ---------------- generic tiled SGEMM:  C[M,Nc] = Aload(M,K) @ B[Nc,K]^T + bias -------
// AMODE 0: plain A
// AMODE 1: row<Nsplit -> A, else A2[row-Nsplit]  (vnode embed substitution)
// AMODE 2: k<512 -> A[row], else A[Nsplit+map[row]] (cluster-gather concat, K=1024)
// SMODE 0: store C; SMODE 1: row<Nsplit -> C (vec), else C2[row-Nsplit] (scalar, misaligned dst)
template<int BM,int BN,int BK,int TM,int TN,int AMODE,int SMODE>
__global__ void sgemm_k(const float* __restrict__ A, const float* __restrict__ A2,
                        const int* __restrict__ map,
                        const float* __restrict__ B, const float* __restrict__ bias,
                        float* __restrict__ C, float* __restrict__ C2,
                        int M, int Nc, int K, int Nsplit)
{
    constexpr int THREADS = (BM/TM)*(BN/TN);
    __shared__ float As[BK][BM];
    __shared__ float Bs[BK][BN];

    const int tid = threadIdx.x;
    const int bm = blockIdx.y * BM;
    const int bn = blockIdx.x * BN;
    const int tx = tid % (BN/TN);
    const int ty = tid / (BN/TN);

    float acc[TM][TN];
    #pragma unroll
    for (int i = 0; i < TM; i++)
        #pragma unroll
        for (int j = 0; j < TN; j++) acc[i][j] = 0.f;

    constexpr int A_IT = (BM*BK/4) / THREADS;
    constexpr int B_IT = (BN*BK/4) / THREADS;

    for (int k0 = 0; k0 < K; k0 += BK) {
        // ---- load A tile (float4), store transposed As[k][m]
        #pragma unroll
        for (int it = 0; it < A_IT; it++) {
            int id = tid + it*THREADS;
            int r  = id / (BK/4);
            int c4 = id % (BK/4);
            int grow = bm + r;
            int rr = grow < M ? grow : M-1;
            int gk = k0 + c4*4;
            float4 v;
            if (AMODE == 0) {
                v = *reinterpret_cast<const float4*>(A + (size_t)rr*K + gk);
            } else if (AMODE == 1) {
                const float* base = (rr < Nsplit) ? (A + (size_t)rr*K)
                                                  : (A2 + (size_t)(rr - Nsplit)*K);
                v = *reinterpret_cast<const float4*>(base + gk);
            } else {
                const float* p;
                if (gk < 512) p = A + (size_t)rr*512 + gk;
                else          p = A + (size_t)(Nsplit + map[rr])*512 + (gk - 512);
                v = *reinterpret_cast<const float4*>(p);
            }
            As[c4*4+0][r] = v.x; As[c4*4+1][r] = v.y;
            As[c4*4+2][r] = v.z; As[c4*4+3][r] = v.w;
        }
        // ---- load B tile (B is [Nc,K] row-major; Nc multiple of BN, no guard)
        #pragma unroll
        for (int it = 0; it < B_IT; it++) {
            int id = tid + it*THREADS;
            int r  = id / (BK/4);
            int c4 = id % (BK/4);
            float4 v = *reinterpret_cast<const float4*>(B + (size_t)(bn + r)*K + k0 + c4*4);
            Bs[c4*4+0][r] = v.x; Bs[c4*4+1][r] = v.y;
            Bs[c4*4+2][r] = v.z; Bs[c4*4+3][r] = v.w;
        }
        __syncthreads();

        #pragma unroll
        for (int k = 0; k < BK; k++) {
            float ra[TM], rb[TN];
            #pragma unroll
            for (int i = 0; i < TM; i += 4) {
                float4 v = *reinterpret_cast<const float4*>(&As[k][ty*TM + i]);
                ra[i]=v.x; ra[i+1]=v.y; ra[i+2]=v.z; ra[i+3]=v.w;
            }
            #pragma unroll
            for (int j = 0; j < TN; j += 4) {
                float4 v = *reinterpret_cast<const float4*>(&Bs[k][tx*TN + j]);
                rb[j]=v.x; rb[j+1]=v.y; rb[j+2]=v.z; rb[j+3]=v.w;
            }
            #pragma unroll
            for (int i = 0; i < TM; i++)
                #pragma unroll
                for (int j = 0; j < TN; j++)
                    acc[i][j] = fmaf(ra[i], rb[j], acc[i][j]);
        }
        __syncthreads();
    }

    // ---- epilogue
    #pragma unroll
    for (int i = 0; i < TM; i++) {
        int row = bm + ty*TM + i;
        if (row >= M) continue;
        #pragma unroll
        for (int j4 = 0; j4 < TN; j4 += 4) {
            int col = bn + tx*TN + j4;
            float4 bv = *reinterpret_cast<const float4*>(bias + col);
            float4 o;
            o.x = acc[i][j4+0] + bv.x; o.y = acc[i][j4+1] + bv.y;
            o.z = acc[i][j4+2] + bv.z; o.w = acc[i][j4+3] + bv.w;
            if (SMODE == 0) {
                *reinterpret_cast<float4*>(C + (size_t)row*Nc + col) = o;
            } else {
                if (row < Nsplit) {
                    *reinterpret_cast<float4*>(C + (size_t)row*Nc + col) = o;
                } else {
                    float* p = C2 + (size_t)(row - Nsplit)*Nc + col;
                    p[0]=o.x; p[1]=o.y; p[2]=o.z; p[3]=o.w;
                }
            }
        }
    }
}

// ---------------- fused LayerNorm + ELU (+ optional tail bias after ELU), warp/row ----
__global__ void ln_elu_k(const float* __restrict__ in, float* __restrict__ out,
                         const float* __restrict__ g, const float* __restrict__ beta,
                         const float* __restrict__ tail_bias, int M, int Ntail0)
{
    int w = (blockIdx.x * blockDim.x + threadIdx.x) >> 5;
    int lane = threadIdx.x & 31;
    if (w >= M) return;
    const float* row = in + (size_t)w * DD;
    float4 v[4];
    float s = 0.f, sq = 0.f;
    #pragma unroll
    for (int q = 0; q < 4; q++) {
        v[q] = *reinterpret_cast<const float4*>(row + q*128 + lane*4);
        s  += v[q].x + v[q].y + v[q].z + v[q].w;
        sq += v[q].x*v[q].x + v[q].y*v[q].y + v[q].z*v[q].z + v[q].w*v[q].w;
    }
    #pragma unroll
    for (int o = 16; o; o >>= 1) {
        s  += __shfl_xor_sync(0xffffffffu, s,  o);
        sq += __shfl_xor_sync(0xffffffffu, sq, o);
    }
    float mean = s * (1.f/512.f);
    float var  = sq * (1.f/512.f) - mean*mean;
    float inv  = rsqrtf(var + 1e-5f);
    float* orow = out + (size_t)w * DD;
    bool tail = (tail_bias != nullptr) && (w >= Ntail0);
    #pragma unroll
    for (int q = 0; q < 4; q++) {
        int c = q*128 + lane*4;
        float4 gv = *reinterpret_cast<const float4*>(g + c);
        float4 bv = *reinterpret_cast<const float4*>(beta + c);
        float4 o;
        o.x = elu1((v[q].x - mean)*inv*gv.x + bv.x);
        o.y = elu1((v[q].y - mean)*inv*gv.y + bv.y);
        o.z = elu1((v[q].z - mean)*inv*gv.z + bv.z);
        o.w = elu1((v[q].w - mean)*inv*gv.w + bv.w);
        if (tail) {
            float4 tb = *reinterpret_cast<const float4*>(tail_bias + (size_t)(w - Ntail0)*DD + c);
            o.x += tb.x; o.y += tb.y; o.z += tb.z; o.w += tb.w;
        }
        *reinterpret_cast<float4*>(orow + c) = o;
    }
}

// ---------------- dst[64,64] = h_tail @ Wd^T + bd + attn_bias, stored TRANSPOSED -----
__global__ void dst_k(const float* __restrict__ h_tail, const float* __restrict__ Wd,
                      const float* __restrict__ bd, const float* __restrict__ ab,
                      float* __restrict__ dstT)
{
    int idx = blockIdx.x * blockDim.x + threadIdx.x;
    if (idx >= 64*64) return;
    int j = idx >> 6;   // vnode
    int a = idx & 63;   // att dim
    const float* hr = h_tail + (size_t)j*DD;
    const float* wr = Wd + (size_t)a*DD;
    float s = 0.f;
    for (int d = 0; d < DD; d += 4) {
        float4 hv = *reinterpret_cast<const float4*>(hr + d);
        float4 wv = *reinterpret_cast<const float4*>(wr + d);
        s = fmaf(hv.x, wv.x, s); s = fmaf(hv.y, wv.y, s);
        s = fmaf(hv.z, wv.z, s); s = fmaf(hv.w, wv.w, s);
    }
    s += bd[a] + ab[j*64 + a];
    dstT[a*64 + j] = s;  // dstT[att][vnode]
}

// ---------------- per-row argmax of src @ dst^T (softmax/leaky_relu are monotone) ----
__global__ void argmax_k(const float* __restrict__ src, const float* __restrict__ dstT,
                         int* __restrict__ cmap, float* __restrict__ map_out, int Nrows)
{
    __shared__ float sdT[64*64];
    __shared__ float ssrc[8][64];
    int tid = threadIdx.x;
    for (int i = tid; i < 64*64; i += blockDim.x) sdT[i] = dstT[i];
    __syncthreads();
    int warp = tid >> 5, lane = tid & 31;
    int row0 = blockIdx.x * 64;
    for (int r = warp; r < 64; r += 8) {
        int row = row0 + r;
        if (row >= Nrows) break;
        ssrc[warp][lane]      = src[(size_t)row*64 + lane];
        ssrc[warp][lane + 32] = src[(size_t)row*64 + lane + 32];
        __syncwarp();
        float a = 0.f, b = 0.f;
        #pragma unroll
        for (int k = 0; k < 64; k++) {
            float sv = ssrc[warp][k];
            a = fmaf(sv, sdT[k*64 + lane],      a);
            b = fmaf(sv, sdT[k*64 + lane + 32], b);
        }
        float bv; int bi;
        if (b > a) { bv = b; bi = lane + 32; } else { bv = a; bi = lane; }
        #pragma unroll
        for (int o = 16; o; o >>= 1) {
            float ov = __shfl_xor_sync(0xffffffffu, bv, o);
            int   oi = __shfl_xor_sync(0xffffffffu, bi, o);
            if (ov > bv || (ov == bv && oi < bi)) { bv = ov; bi = oi; }
        }
        if (lane == 0) { cmap[row] = bi; map_out[row] = (float)bi; }
        __syncwarp();
    }
}

// ---------------- tail fixups: h += vnode_bias_dcd (tail rows), cmap tail, loss=0 ----
__global__ void tail_setup_k(float* __restrict__ h, const float* __restrict__ vbd,
                             int* __restrict__ cmap, float* __restrict__ lossp, int Ntail0)
{
    int idx = blockIdx.x * blockDim.x + threadIdx.x;
    if (idx < PV * DD) h[(size_t)Ntail0 * DD + idx] += vbd[idx];
    if (idx < PV) cmap[Ntail0 + idx] = idx;
    if (idx == 0) *lossp = 0.f;
}

extern "C" void kernel_launch(void* const* d_in, const int* in_sizes, int n_in,
                              void* d_out, int out_size)
{
    const float* x    = (const float*)d_in[0];
    const float* vemb = (const float*)d_in[1];
    const float* vbh  = (const float*)d_in[2];
    const float* vbd  = (const float*)d_in[3];
    const float* Win  = (const float*)d_in[4];
    const float* bin  = (const float*)d_in[5];
    const float* ghid = (const float*)d_in[6];
    const float* bhid = (const float*)d_in[7];
    const float* Wenc = (const float*)d_in[8];
    const float* benc = (const float*)d_in[9];
    const float* gdcd = (const float*)d_in[10];
    const float* bdcd = (const float*)d_in[11];
    const float* Ws   = (const float*)d_in[12];
    const float* bs   = (const float*)d_in[13];
    const float* Wd   = (const float*)d_in[14];
    const float* bd   = (const float*)d_in[15];
    const float* ab   = (const float*)d_in[16];
    const float* Wag  = (const float*)d_in[17];
    const float* bag  = (const float*)d_in[18];
    const float* Wout = (const float*)d_in[19];
    const float* bout = (const float*)d_in[20];

    const int M = in_sizes[0] / DD;     // N + P
    const int N = M - PV;

    float *bufA, *bufB, *srcb, *dstT; int* cmap;
    cudaGetSymbolAddress((void**)&bufA, g_bufA);
    cudaGetSymbolAddress((void**)&bufB, g_bufB);
    cudaGetSymbolAddress((void**)&srcb, g_srcb);
    cudaGetSymbolAddress((void**)&dstT, g_dstT);
    cudaGetSymbolAddress((void**)&cmap, g_cmap);

    float* out   = (float*)d_out;
    float* lossp = out + (size_t)N * DD;
    float* reps  = lossp + 1;
    float* mapo  = reps + (size_t)PV * DD;

    dim3 blk(256);
    const int gm = (M + 127) / 128;

    // h = elu(ln(x' @ Win^T + bin)); x' has vnode_embed substituted in tail rows
    sgemm_k<128,128,16,8,8,1,0><<<dim3(DD/128, gm), blk>>>(x, vemb, nullptr, Win, bin, bufA, nullptr, M, DD, DD, N);
    ln_elu_k<<<(M + 7) / 8, 256>>>(bufA, bufB, ghid, bhid, vbh, M, N);     // + vnode_bias_hid on tail

    // h = elu(ln(h @ Wenc^T + benc))
    sgemm_k<128,128,16,8,8,0,0><<<dim3(DD/128, gm), blk>>>(bufB, nullptr, nullptr, Wenc, benc, bufA, nullptr, M, DD, DD, N);
    ln_elu_k<<<(M + 7) / 8, 256>>>(bufA, bufB, gdcd, bdcd, nullptr, M, N);

    // src = h[:N] @ Ws^T + bs ;  dstT ;  cluster argmax
    sgemm_k<128,64,16,8,4,0,0><<<dim3(1, (N + 127) / 128), blk>>>(bufB, nullptr, nullptr, Ws, bs, srcb, nullptr, N, 64, DD, N);
    dst_k<<<16, 256>>>(bufB + (size_t)N * DD, Wd, bd, ab, dstT);
    argmax_k<<<(N + 63) / 64, 256>>>(srcb, dstT, cmap, mapo, N);

    // tail: h[-P:] += vnode_bias_dcd ; cmap tail identity ; loss = 0
    tail_setup_k<<<(PV * DD + 255) / 256, 256>>>(bufB, vbd, cmap, lossp, N);

    // h3 = elu(ln([h | h[N+map]] @ Wag^T + bag))  (gather fused into A-loader, K=1024)
    sgemm_k<128,128,16,8,8,2,0><<<dim3(DD/128, gm), blk>>>(bufB, nullptr, cmap, Wag, bag, bufA, nullptr, M, DD, 2*DD, N);
    ln_elu_k<<<(M + 7) / 8, 256>>>(bufA, bufB, gdcd, bdcd, nullptr, M, N);

    // y = h3 @ Wout^T + bout ; split-store into out / cluster_reps regions of d_out
    sgemm_k<128,128,16,8,8,0,1><<<dim3(DD/128, gm), blk>>>(bufB, nullptr, nullptr, Wout, bout, out, reps, M, DD, DD, N);
}

// round 6
// speedup vs baseline: 1.4772x; 1.4772x over previous
#include <cuda_runtime.h>
#include <cuda_fp16.h>
#include <math.h>
#include <cstdint>

#define DD 512
#define MAXM 100064
#define PV 64

// ---------------- scratch ----------------
__device__ __align__(16) float g_bufA[(size_t)MAXM * DD];
__device__ __align__(16) float g_bufB[(size_t)MAXM * DD];
__device__ __align__(16) float g_srcb[(size_t)MAXM * 64];
__device__ __align__(16) float g_dstT[64 * 64];
__device__ int g_cmap[MAXM];

__device__ __forceinline__ float elu1(float x) { return x > 0.f ? x : expm1f(x); }

// ======================================================================================
// fp32 FFMA SGEMM — BYTE-IDENTICAL arithmetic to the round-0 passing kernel.
// Used for the argmax-upstream GEMMs (GEMM1, GEMM2, src) so the cluster argmax
// reproduces the reference decision exactly (the critical row is a near-tie).
// ======================================================================================
template<int BM,int BN,int BK,int TM,int TN,int AMODE,int SMODE>
__global__ void sgemm_k(const float* __restrict__ A, const float* __restrict__ A2,
                        const int* __restrict__ map,
                        const float* __restrict__ B, const float* __restrict__ bias,
                        float* __restrict__ C, float* __restrict__ C2,
                        int M, int Nc, int K, int Nsplit)
{
    constexpr int THREADS = (BM/TM)*(BN/TN);
    __shared__ float As[BK][BM];
    __shared__ float Bs[BK][BN];

    const int tid = threadIdx.x;
    const int bm = blockIdx.y * BM;
    const int bn = blockIdx.x * BN;
    const int tx = tid % (BN/TN);
    const int ty = tid / (BN/TN);

    float acc[TM][TN];
    #pragma unroll
    for (int i = 0; i < TM; i++)
        #pragma unroll
        for (int j = 0; j < TN; j++) acc[i][j] = 0.f;

    constexpr int A_IT = (BM*BK/4) / THREADS;
    constexpr int B_IT = (BN*BK/4) / THREADS;

    for (int k0 = 0; k0 < K; k0 += BK) {
        #pragma unroll
        for (int it = 0; it < A_IT; it++) {
            int id = tid + it*THREADS;
            int r  = id / (BK/4);
            int c4 = id % (BK/4);
            int grow = bm + r;
            int rr = grow < M ? grow : M-1;
            int gk = k0 + c4*4;
            float4 v;
            if (AMODE == 0) {
                v = *reinterpret_cast<const float4*>(A + (size_t)rr*K + gk);
            } else if (AMODE == 1) {
                const float* base = (rr < Nsplit) ? (A + (size_t)rr*K)
                                                  : (A2 + (size_t)(rr - Nsplit)*K);
                v = *reinterpret_cast<const float4*>(base + gk);
            } else {
                const float* p;
                if (gk < 512) p = A + (size_t)rr*512 + gk;
                else          p = A + (size_t)(Nsplit + map[rr])*512 + (gk - 512);
                v = *reinterpret_cast<const float4*>(p);
            }
            As[c4*4+0][r] = v.x; As[c4*4+1][r] = v.y;
            As[c4*4+2][r] = v.z; As[c4*4+3][r] = v.w;
        }
        #pragma unroll
        for (int it = 0; it < B_IT; it++) {
            int id = tid + it*THREADS;
            int r  = id / (BK/4);
            int c4 = id % (BK/4);
            float4 v = *reinterpret_cast<const float4*>(B + (size_t)(bn + r)*K + k0 + c4*4);
            Bs[c4*4+0][r] = v.x; Bs[c4*4+1][r] = v.y;
            Bs[c4*4+2][r] = v.z; Bs[c4*4+3][r] = v.w;
        }
        __syncthreads();

        #pragma unroll
        for (int k = 0; k < BK; k++) {
            float ra[TM], rb[TN];
            #pragma unroll
            for (int i = 0; i < TM; i += 4) {
                float4 v = *reinterpret_cast<const float4*>(&As[k][ty*TM + i]);
                ra[i]=v.x; ra[i+1]=v.y; ra[i+2]=v.z; ra[i+3]=v.w;
            }
            #pragma unroll
            for (int j = 0; j < TN; j += 4) {
                float4 v = *reinterpret_cast<const float4*>(&Bs[k][tx*TN + j]);
                rb[j]=v.x; rb[j+1]=v.y; rb[j+2]=v.z; rb[j+3]=v.w;
            }
            #pragma unroll
            for (int i = 0; i < TM; i++)
                #pragma unroll
                for (int j = 0; j < TN; j++)
                    acc[i][j] = fmaf(ra[i], rb[j], acc[i][j]);
        }
        __syncthreads();
    }

    #pragma unroll
    for (int i = 0; i < TM; i++) {
        int row = bm + ty*TM + i;
        if (row >= M) continue;
        #pragma unroll
        for (int j4 = 0; j4 < TN; j4 += 4) {
            int col = bn + tx*TN + j4;
            float4 bv = *reinterpret_cast<const float4*>(bias + col);
            float4 o;
            o.x = acc[i][j4+0] + bv.x; o.y = acc[i][j4+1] + bv.y;
            o.z = acc[i][j4+2] + bv.z; o.w = acc[i][j4+3] + bv.w;
            if (SMODE == 0) {
                *reinterpret_cast<float4*>(C + (size_t)row*Nc + col) = o;
            } else {
                if (row < Nsplit) {
                    *reinterpret_cast<float4*>(C + (size_t)row*Nc + col) = o;
                } else {
                    float* p = C2 + (size_t)(row - Nsplit)*Nc + col;
                    p[0]=o.x; p[1]=o.y; p[2]=o.z; p[3]=o.w;
                }
            }
        }
    }
}

// ======================================================================================
// HMMA fp16 2-way-split (3 products) GEMM — for the argmax-DOWNSTREAM GEMMs
// (aggr, out). Error ~1e-5, smooth contribution only.
// ======================================================================================
__device__ __forceinline__ void split4(float4 v, unsigned& h0, unsigned& h1,
                                       unsigned& l0, unsigned& l1) {
    __half hx = __float2half_rn(v.x), hy = __float2half_rn(v.y);
    __half hz = __float2half_rn(v.z), hw = __float2half_rn(v.w);
    __half2 H0 = __halves2half2(hx, hy), H1 = __halves2half2(hz, hw);
    float lx = v.x - __half2float(hx), ly = v.y - __half2float(hy);
    float lz = v.z - __half2float(hz), lw = v.w - __half2float(hw);
    __half2 L0 = __floats2half2_rn(lx, ly), L1 = __floats2half2_rn(lz, lw);
    h0 = *reinterpret_cast<unsigned*>(&H0); h1 = *reinterpret_cast<unsigned*>(&H1);
    l0 = *reinterpret_cast<unsigned*>(&L0); l1 = *reinterpret_cast<unsigned*>(&L1);
}

__device__ __forceinline__ void mma16816(float* d, const unsigned* a, const unsigned* b) {
    asm("mma.sync.aligned.m16n8k16.row.col.f32.f16.f16.f32 "
        "{%0,%1,%2,%3}, {%4,%5,%6,%7}, {%8,%9}, {%0,%1,%2,%3};"
        : "+f"(d[0]), "+f"(d[1]), "+f"(d[2]), "+f"(d[3])
        : "r"(a[0]), "r"(a[1]), "r"(a[2]), "r"(a[3]), "r"(b[0]), "r"(b[1]));
}

// AMODE: 0 plain / 2 concat-gather (K=1024).  SMODE: 0 normal / 1 split C/C2 store.
template<int BN, int AMODE, int SMODE>
__global__ void __launch_bounds__(256, 1) hgemm_k(
    const float* __restrict__ A, const float* __restrict__ A2, const int* __restrict__ map,
    const float* __restrict__ B, const float* __restrict__ bias,
    float* __restrict__ C, float* __restrict__ C2,
    int M, int Nc, int K, int Nsplit)
{
    extern __shared__ char sm[];
    constexpr int NT = 4;
    constexpr int WN = BN / 32;
    constexpr int WM = 8 / WN;
    constexpr int MT = 128 / (WM * 16);
    constexpr int ASZ = 8192;
    constexpr int BSZ = BN * 64;
    constexpr int STAGE = 2 * ASZ + 2 * BSZ;
    constexpr int NBT = BN / 8;

    const int tid = threadIdx.x;
    const int wid = tid >> 5, lane = tid & 31;
    const int grp = lane >> 2, tig = lane & 3;
    const int bm = blockIdx.y * 128, bn = blockIdx.x * BN;
    const int wm = wid / WN, wn = wid % WN;

    float acc[MT][NT][4];
    #pragma unroll
    for (int i = 0; i < MT; i++)
        #pragma unroll
        for (int j = 0; j < NT; j++)
            #pragma unroll
            for (int q = 0; q < 4; q++) acc[i][j][q] = 0.f;

    float4 ra[4], rb[BN / 32];

    auto loadA = [&](int k0) {
        #pragma unroll
        for (int it = 0; it < 4; it++) {
            int id = tid + it * 256;
            int r = id >> 3, q = id & 7;
            int rr = bm + r; if (rr >= M) rr = M - 1;
            int gk = k0 + q * 4;
            const float* p;
            if (AMODE == 0)      p = A + (size_t)rr * K + gk;
            else                 p = (gk < 512) ? A + (size_t)rr * 512 + gk
                                                : A + (size_t)(Nsplit + map[rr]) * 512 + (gk - 512);
            ra[it] = *reinterpret_cast<const float4*>(p);
        }
        #pragma unroll
        for (int it = 0; it < BN / 32; it++) {
            int id = tid + it * 256;
            int r = id >> 3, q = id & 7;
            rb[it] = *reinterpret_cast<const float4*>(B + (size_t)(bn + r) * K + k0 + q * 4);
        }
    };

    auto storeStage = [&](char* stg) {
        #pragma unroll
        for (int it = 0; it < 4; it++) {
            int id = tid + it * 256;
            int r = id >> 3, q = id & 7;
            int kc = q * 4, ks = kc >> 4, kcw = kc & 15;
            int mt = r >> 4;
            int lane0 = (r & 7) * 4 + ((kcw & 7) >> 1);
            int reg = ((r >> 3) & 1) + ((kcw >> 3) << 1);
            unsigned h0, h1, l0, l1; split4(ra[it], h0, h1, l0, l1);
            unsigned off = ((ks * 8 + mt) * 32 + lane0) * 16 + reg * 4;
            *reinterpret_cast<unsigned*>(stg + off) = h0;
            *reinterpret_cast<unsigned*>(stg + off + 16) = h1;
            *reinterpret_cast<unsigned*>(stg + ASZ + off) = l0;
            *reinterpret_cast<unsigned*>(stg + ASZ + off + 16) = l1;
        }
        #pragma unroll
        for (int it = 0; it < BN / 32; it++) {
            int id = tid + it * 256;
            int r = id >> 3, q = id & 7;
            int kc = q * 4, ks = kc >> 4, kcw = kc & 15;
            int nt = r >> 3;
            int lane0 = (r & 7) * 4 + ((kcw & 7) >> 1);
            int reg = kcw >> 3;
            unsigned h0, h1, l0, l1; split4(rb[it], h0, h1, l0, l1);
            unsigned off = ((ks * NBT + nt) * 32 + lane0) * 8 + reg * 4;
            *reinterpret_cast<unsigned*>(stg + 2 * ASZ + off) = h0;
            *reinterpret_cast<unsigned*>(stg + 2 * ASZ + off + 8) = h1;
            *reinterpret_cast<unsigned*>(stg + 2 * ASZ + BSZ + off) = l0;
            *reinterpret_cast<unsigned*>(stg + 2 * ASZ + BSZ + off + 8) = l1;
        }
    };

    loadA(0);
    storeStage(sm);
    __syncthreads();

    const int NCH = K / 32;
    for (int i = 0; i < NCH; i++) {
        if (i + 1 < NCH) loadA((i + 1) * 32);
        char* stg = sm + (i & 1) * STAGE;
        #pragma unroll
        for (int ks = 0; ks < 2; ks++) {
            unsigned Ah[MT][4], Al[MT][4], Bh[NT][2], Bl[NT][2];
            #pragma unroll
            for (int t = 0; t < MT; t++) {
                int mt = wm * MT + t;
                unsigned off = ((ks * 8 + mt) * 32 + lane) * 16;
                uint4 h = *reinterpret_cast<const uint4*>(stg + off);
                uint4 l = *reinterpret_cast<const uint4*>(stg + ASZ + off);
                Ah[t][0] = h.x; Ah[t][1] = h.y; Ah[t][2] = h.z; Ah[t][3] = h.w;
                Al[t][0] = l.x; Al[t][1] = l.y; Al[t][2] = l.z; Al[t][3] = l.w;
            }
            #pragma unroll
            for (int t = 0; t < NT; t++) {
                int nt = wn * NT + t;
                unsigned off = ((ks * NBT + nt) * 32 + lane) * 8;
                uint2 h = *reinterpret_cast<const uint2*>(stg + 2 * ASZ + off);
                uint2 l = *reinterpret_cast<const uint2*>(stg + 2 * ASZ + BSZ + off);
                Bh[t][0] = h.x; Bh[t][1] = h.y;
                Bl[t][0] = l.x; Bl[t][1] = l.y;
            }
            #pragma unroll
            for (int ti = 0; ti < MT; ti++)
                #pragma unroll
                for (int tj = 0; tj < NT; tj++) {
                    mma16816(acc[ti][tj], Ah[ti], Bh[tj]);
                    mma16816(acc[ti][tj], Ah[ti], Bl[tj]);
                    mma16816(acc[ti][tj], Al[ti], Bh[tj]);
                }
        }
        __syncthreads();
        if (i + 1 < NCH) {
            storeStage(sm + ((i + 1) & 1) * STAGE);
            __syncthreads();
        }
    }

    #pragma unroll
    for (int i = 0; i < MT; i++) {
        #pragma unroll
        for (int j = 0; j < NT; j++) {
            int col = bn + (wn * NT + j) * 8 + tig * 2;
            float bx = bias[col], by = bias[col + 1];
            int row0 = bm + (wm * MT + i) * 16 + grp;
            float2 v0 = make_float2(acc[i][j][0] + bx, acc[i][j][1] + by);
            float2 v1 = make_float2(acc[i][j][2] + bx, acc[i][j][3] + by);
            #pragma unroll
            for (int h = 0; h < 2; h++) {
                int row = row0 + h * 8;
                float2 v = h ? v1 : v0;
                if (row >= M) continue;
                if (SMODE == 0 || row < Nsplit) {
                    *reinterpret_cast<float2*>(C + (size_t)row * Nc + col) = v;
                } else {
                    float* p = C2 + (size_t)(row - Nsplit) * Nc + col;
                    p[0] = v.x; p[1] = v.y;
                }
            }
        }
    }
}

// ---------------- fused LayerNorm + ELU (+ optional tail bias), warp/row ----------------
__global__ void ln_elu_k(const float* __restrict__ in, float* __restrict__ out,
                         const float* __restrict__ g, const float* __restrict__ beta,
                         const float* __restrict__ tail_bias, int M, int Ntail0)
{
    int w = (blockIdx.x * blockDim.x + threadIdx.x) >> 5;
    int lane = threadIdx.x & 31;
    if (w >= M) return;
    const float* row = in + (size_t)w * DD;
    float4 v[4];
    float s = 0.f, sq = 0.f;
    #pragma unroll
    for (int q = 0; q < 4; q++) {
        v[q] = *reinterpret_cast<const float4*>(row + q * 128 + lane * 4);
        s  += v[q].x + v[q].y + v[q].z + v[q].w;
        sq += v[q].x * v[q].x + v[q].y * v[q].y + v[q].z * v[q].z + v[q].w * v[q].w;
    }
    #pragma unroll
    for (int o = 16; o; o >>= 1) {
        s  += __shfl_xor_sync(0xffffffffu, s,  o);
        sq += __shfl_xor_sync(0xffffffffu, sq, o);
    }
    float mean = s * (1.f / 512.f);
    float var  = sq * (1.f / 512.f) - mean * mean;
    float inv  = rsqrtf(var + 1e-5f);
    float* orow = out + (size_t)w * DD;
    bool tail = (tail_bias != nullptr) && (w >= Ntail0);
    #pragma unroll
    for (int q = 0; q < 4; q++) {
        int c = q * 128 + lane * 4;
        float4 gv = *reinterpret_cast<const float4*>(g + c);
        float4 bv = *reinterpret_cast<const float4*>(beta + c);
        float4 o;
        o.x = elu1((v[q].x - mean) * inv * gv.x + bv.x);
        o.y = elu1((v[q].y - mean) * inv * gv.y + bv.y);
        o.z = elu1((v[q].z - mean) * inv * gv.z + bv.z);
        o.w = elu1((v[q].w - mean) * inv * gv.w + bv.w);
        if (tail) {
            float4 tb = *reinterpret_cast<const float4*>(tail_bias + (size_t)(w - Ntail0) * DD + c);
            o.x += tb.x; o.y += tb.y; o.z += tb.z; o.w += tb.w;
        }
        *reinterpret_cast<float4*>(orow + c) = o;
    }
}

// ---------------- dst[64,64] = h_tail @ Wd^T + bd + attn_bias, stored transposed ----------
__global__ void dst_k(const float* __restrict__ h_tail, const float* __restrict__ Wd,
                      const float* __restrict__ bd, const float* __restrict__ ab,
                      float* __restrict__ dstT)
{
    int idx = blockIdx.x * blockDim.x + threadIdx.x;
    if (idx >= 64 * 64) return;
    int j = idx >> 6;
    int a = idx & 63;
    const float* hr = h_tail + (size_t)j * DD;
    const float* wr = Wd + (size_t)a * DD;
    float s = 0.f;
    for (int d = 0; d < DD; d += 4) {
        float4 hv = *reinterpret_cast<const float4*>(hr + d);
        float4 wv = *reinterpret_cast<const float4*>(wr + d);
        s = fmaf(hv.x, wv.x, s); s = fmaf(hv.y, wv.y, s);
        s = fmaf(hv.z, wv.z, s); s = fmaf(hv.w, wv.w, s);
    }
    s += bd[a] + ab[j * 64 + a];
    dstT[a * 64 + j] = s;
}

// ---------------- per-row argmax of src @ dst^T (softmax/leaky_relu monotone) -------------
__global__ void argmax_k(const float* __restrict__ src, const float* __restrict__ dstT,
                         int* __restrict__ cmap, float* __restrict__ map_out, int Nrows)
{
    __shared__ float sdT[64 * 64];
    __shared__ float ssrc[8][64];
    int tid = threadIdx.x;
    for (int i = tid; i < 64 * 64; i += blockDim.x) sdT[i] = dstT[i];
    __syncthreads();
    int warp = tid >> 5, lane = tid & 31;
    int row0 = blockIdx.x * 64;
    for (int r = warp; r < 64; r += 8) {
        int row = row0 + r;
        if (row >= Nrows) break;
        ssrc[warp][lane]      = src[(size_t)row * 64 + lane];
        ssrc[warp][lane + 32] = src[(size_t)row * 64 + lane + 32];
        __syncwarp();
        float a = 0.f, b = 0.f;
        #pragma unroll
        for (int k = 0; k < 64; k++) {
            float sv = ssrc[warp][k];
            a = fmaf(sv, sdT[k * 64 + lane],      a);
            b = fmaf(sv, sdT[k * 64 + lane + 32], b);
        }
        float bv; int bi;
        if (b > a) { bv = b; bi = lane + 32; } else { bv = a; bi = lane; }
        #pragma unroll
        for (int o = 16; o; o >>= 1) {
            float ov = __shfl_xor_sync(0xffffffffu, bv, o);
            int   oi = __shfl_xor_sync(0xffffffffu, bi, o);
            if (ov > bv || (ov == bv && oi < bi)) { bv = ov; bi = oi; }
        }
        if (lane == 0) { cmap[row] = bi; map_out[row] = (float)bi; }
        __syncwarp();
    }
}

// ---------------- tail fixups ----------------
__global__ void tail_setup_k(float* __restrict__ h, const float* __restrict__ vbd,
                             int* __restrict__ cmap, float* __restrict__ lossp, int Ntail0)
{
    int idx = blockIdx.x * blockDim.x + threadIdx.x;
    if (idx < PV * DD) h[(size_t)Ntail0 * DD + idx] += vbd[idx];
    if (idx < PV) cmap[Ntail0 + idx] = idx;
    if (idx == 0) *lossp = 0.f;
}

extern "C" void kernel_launch(void* const* d_in, const int* in_sizes, int n_in,
                              void* d_out, int out_size)
{
    const float* x    = (const float*)d_in[0];
    const float* vemb = (const float*)d_in[1];
    const float* vbh  = (const float*)d_in[2];
    const float* vbd  = (const float*)d_in[3];
    const float* Win  = (const float*)d_in[4];
    const float* bin  = (const float*)d_in[5];
    const float* ghid = (const float*)d_in[6];
    const float* bhid = (const float*)d_in[7];
    const float* Wenc = (const float*)d_in[8];
    const float* benc = (const float*)d_in[9];
    const float* gdcd = (const float*)d_in[10];
    const float* bdcd = (const float*)d_in[11];
    const float* Ws   = (const float*)d_in[12];
    const float* bs   = (const float*)d_in[13];
    const float* Wd   = (const float*)d_in[14];
    const float* bd   = (const float*)d_in[15];
    const float* ab   = (const float*)d_in[16];
    const float* Wag  = (const float*)d_in[17];
    const float* bag  = (const float*)d_in[18];
    const float* Wout = (const float*)d_in[19];
    const float* bout = (const float*)d_in[20];

    const int M = in_sizes[0] / DD;
    const int N = M - PV;

    float *bufA, *bufB, *srcb, *dstT; int* cmap;
    cudaGetSymbolAddress((void**)&bufA, g_bufA);
    cudaGetSymbolAddress((void**)&bufB, g_bufB);
    cudaGetSymbolAddress((void**)&srcb, g_srcb);
    cudaGetSymbolAddress((void**)&dstT, g_dstT);
    cudaGetSymbolAddress((void**)&cmap, g_cmap);

    float* out   = (float*)d_out;
    float* lossp = out + (size_t)N * DD;
    float* reps  = lossp + 1;
    float* mapo  = reps + (size_t)PV * DD;

    constexpr int SMH = 2 * (2 * 8192 + 2 * 128 * 64);  // 65536 (hgemm BN=128, 2-way split)
    cudaFuncSetAttribute(hgemm_k<128,2,0>, cudaFuncAttributeMaxDynamicSharedMemorySize, SMH);
    cudaFuncSetAttribute(hgemm_k<128,0,1>, cudaFuncAttributeMaxDynamicSharedMemorySize, SMH);

    const int gm = (M + 127) / 128;
    dim3 blk(256);

    // ---- argmax-upstream path: EXACT round-0 fp32 arithmetic ----
    // h = elu(ln(x' @ Win^T + bin)); x' has vnode_embed substituted in tail rows
    sgemm_k<128,128,16,8,8,1,0><<<dim3(DD/128, gm), blk>>>(x, vemb, nullptr, Win, bin, bufA, nullptr, M, DD, DD, N);
    ln_elu_k<<<(M + 7) / 8, 256>>>(bufA, bufB, ghid, bhid, vbh, M, N);

    // h = elu(ln(h @ Wenc^T + benc))
    sgemm_k<128,128,16,8,8,0,0><<<dim3(DD/128, gm), blk>>>(bufB, nullptr, nullptr, Wenc, benc, bufA, nullptr, M, DD, DD, N);
    ln_elu_k<<<(M + 7) / 8, 256>>>(bufA, bufB, gdcd, bdcd, nullptr, M, N);

    // src = h[:N] @ Ws^T + bs ; dstT ; argmax -> cluster map
    sgemm_k<128,64,16,8,4,0,0><<<dim3(1, (N + 127) / 128), blk>>>(bufB, nullptr, nullptr, Ws, bs, srcb, nullptr, N, 64, DD, N);
    dst_k<<<16, 256>>>(bufB + (size_t)N * DD, Wd, bd, ab, dstT);
    argmax_k<<<(N + 63) / 64, 256>>>(srcb, dstT, cmap, mapo, N);

    // tail: h[-P:] += vnode_bias_dcd ; cmap tail identity ; loss = 0
    tail_setup_k<<<(PV * DD + 255) / 256, 256>>>(bufB, vbd, cmap, lossp, N);

    // ---- argmax-downstream path: HMMA (smooth ~1e-5 error) ----
    // h3 = elu(ln([h | h[N+map]] @ Wag^T + bag))  (gather fused into A-loader, K=1024)
    hgemm_k<128,2,0><<<dim3(DD/128, gm), blk, SMH>>>(bufB, nullptr, cmap, Wag, bag, bufA, nullptr, M, DD, 2*DD, N);
    ln_elu_k<<<(M + 7) / 8, 256>>>(bufA, bufB, gdcd, bdcd, nullptr, M, N);

    // y = h3 @ Wout^T + bout ; split-store into out / cluster_reps regions
    hgemm_k<128,0,1><<<dim3(DD/128, gm), blk, SMH>>>(bufB, nullptr, nullptr, Wout, bout, out, reps, M, DD, DD, N);
}